// round 5
// baseline (speedup 1.0000x reference)
#include <cuda_runtime.h>
#include <math.h>

#define ALPHA 0.2f

constexpr int B = 8;
constexpr int N = 2048;
constexpr int C = 128;
constexpr int SEG = 128;
constexpr int NSEG = N / SEG;   // 16

// ---------------- device scratch (static, allowed) ----------------
__device__ float g_h[B * N * C];          // h = text @ W
__device__ float g_s1[B * N];
__device__ float g_s2[B * N];
__device__ float g_s2s[B * N];            // sorted s2 (ascending) per batch
__device__ int   g_sidx[B * N];           // permutation: sorted rank -> original row
__device__ float g_u[B * N];              // exp(s2s - m)
__device__ float g_v[B * N];              // exp(ALPHA*(s2s - m))
__device__ float g_Cf[B * N * C];         // forward (v-weighted) inclusive seg-scan of h[sidx]
__device__ float g_Cb[B * N * C];         // backward (u-weighted) inclusive seg-scan of h[sidx]
__device__ float g_e2c[B * N];            // scalar forward seg-scan of v
__device__ float g_e1c[B * N];            // scalar backward seg-scan of u
__device__ float g_Of[B * NSEG * C];      // forward segment offsets (sum of full segs before)
__device__ float g_Ob[B * NSEG * C];      // backward segment offsets (sum of full segs after)
__device__ float g_of_sc[B * NSEG];
__device__ float g_ob_sc[B * NSEG];
__device__ float g_m[B];                  // per-batch max of s2

// ---------------- kernel 1: h = X @ W, fused s1 = h.a1, s2 = h.a2 ----------------
// X: [B*N, C] row-major, W: [C, C] row-major, a: [2C]
__global__ __launch_bounds__(256) void gemm_s_kernel(
    const float* __restrict__ X, const float* __restrict__ W,
    const float* __restrict__ a)
{
    __shared__ float Xs[64][C];     // 32 KB
    __shared__ float Ws[16][C];     // 8 KB

    const int t    = threadIdx.x;
    const int lane = t & 31;
    const int w    = t >> 5;
    const int cbase = lane * 4;     // 4 output columns
    const int rbase = w * 8;        // 8 output rows
    const int bm = blockIdx.x * 64; // global row base

    // load X tile (64x128 floats = 2048 float4, 8 per thread)
    {
        const float4* Xg4 = reinterpret_cast<const float4*>(X + (size_t)bm * C);
        float4* Xs4 = reinterpret_cast<float4*>(&Xs[0][0]);
#pragma unroll
        for (int i = 0; i < 8; i++) Xs4[t + i * 256] = Xg4[t + i * 256];
    }

    float acc[8][4];
#pragma unroll
    for (int i = 0; i < 8; i++)
#pragma unroll
        for (int j = 0; j < 4; j++) acc[i][j] = 0.f;

    for (int k0 = 0; k0 < C; k0 += 16) {
        __syncthreads();   // X ready (first iter) / previous W chunk consumed
        {
            const float4* Wg4 = reinterpret_cast<const float4*>(W + (size_t)k0 * C);
            float4* Ws4 = reinterpret_cast<float4*>(&Ws[0][0]);
#pragma unroll
            for (int i = 0; i < 2; i++) Ws4[t + i * 256] = Wg4[t + i * 256];
        }
        __syncthreads();
#pragma unroll
        for (int kk = 0; kk < 16; kk++) {
            float4 wv = *reinterpret_cast<float4*>(&Ws[kk][cbase]);
#pragma unroll
            for (int i = 0; i < 8; i++) {
                float x = Xs[rbase + i][k0 + kk];
                acc[i][0] += x * wv.x;
                acc[i][1] += x * wv.y;
                acc[i][2] += x * wv.z;
                acc[i][3] += x * wv.w;
            }
        }
    }

    // store h
#pragma unroll
    for (int i = 0; i < 8; i++) {
        float4 o = make_float4(acc[i][0], acc[i][1], acc[i][2], acc[i][3]);
        *reinterpret_cast<float4*>(&g_h[(size_t)(bm + rbase + i) * C + cbase]) = o;
    }

    // fused s1, s2 (warp covers all 128 cols of its 8 rows)
    float4 a1v = *reinterpret_cast<const float4*>(&a[cbase]);
    float4 a2v = *reinterpret_cast<const float4*>(&a[C + cbase]);
#pragma unroll
    for (int i = 0; i < 8; i++) {
        float p1 = acc[i][0] * a1v.x + acc[i][1] * a1v.y + acc[i][2] * a1v.z + acc[i][3] * a1v.w;
        float p2 = acc[i][0] * a2v.x + acc[i][1] * a2v.y + acc[i][2] * a2v.z + acc[i][3] * a2v.w;
#pragma unroll
        for (int o = 16; o; o >>= 1) {
            p1 += __shfl_xor_sync(0xffffffffu, p1, o);
            p2 += __shfl_xor_sync(0xffffffffu, p2, o);
        }
        if (lane == 0) {
            g_s1[bm + rbase + i] = p1;
            g_s2[bm + rbase + i] = p2;
        }
    }
}

// ---------------- kernel 2: per-batch bitonic sort of s2 + compute u,v ----------------
__global__ __launch_bounds__(1024) void sort_kernel()
{
    __shared__ float key[N];
    __shared__ int   idx[N];
    const int b = blockIdx.x;
    const int t = threadIdx.x;

    for (int e = t; e < N; e += 1024) { key[e] = g_s2[b * N + e]; idx[e] = e; }
    __syncthreads();

    for (int k = 2; k <= N; k <<= 1) {
        for (int j = k >> 1; j > 0; j >>= 1) {
#pragma unroll
            for (int half = 0; half < 2; half++) {
                int e = t + half * 1024;
                int ixj = e ^ j;
                if (ixj > e) {
                    bool up = ((e & k) == 0);
                    float ka = key[e], kb = key[ixj];
                    bool sw = up ? (ka > kb) : (ka < kb);
                    if (sw) {
                        key[e] = kb; key[ixj] = ka;
                        int tmp = idx[e]; idx[e] = idx[ixj]; idx[ixj] = tmp;
                    }
                }
            }
            __syncthreads();
        }
    }

    float m = key[N - 1];   // max (ascending sort)
    for (int e = t; e < N; e += 1024) {
        float s = key[e];
        g_s2s[b * N + e]  = s;
        g_sidx[b * N + e] = idx[e];
        g_u[b * N + e] = expf(s - m);
        g_v[b * N + e] = expf(ALPHA * (s - m));
    }
    if (t == 0) g_m[b] = m;
}

// ---------------- kernel 3: segmented fwd(v)/bwd(u) scans (vector + scalar) ----------------
__global__ __launch_bounds__(256) void scan_kernel()
{
    const int b = blockIdx.y;
    const int s = blockIdx.x;
    const int t = threadIdx.x;

    __shared__ float wv[SEG];
    __shared__ float wu[SEG];
    __shared__ int   sid[SEG];

    const int base = b * N + s * SEG;
    if (t < SEG) { wv[t] = g_v[base + t]; sid[t] = g_sidx[base + t]; }
    else         { wu[t - SEG] = g_u[base + (t - SEG)]; }
    __syncthreads();

    const float* __restrict__ hb = g_h + (size_t)b * N * C;

    if (t < SEG) {                         // forward, v-weighted
        const int f = t;
        float acc = 0.f, sc = 0.f;
#pragma unroll 4
        for (int r = 0; r < SEG; r++) {
            float w = wv[r];
            acc += w * hb[(size_t)sid[r] * C + f];
            sc  += w;
            g_Cf[(size_t)(base + r) * C + f] = acc;
            if (f == 0) g_e2c[base + r] = sc;
        }
    } else {                               // backward, u-weighted
        const int f = t - SEG;
        float acc = 0.f, sc = 0.f;
#pragma unroll 4
        for (int r = SEG - 1; r >= 0; r--) {
            float w = wu[r];
            acc += w * hb[(size_t)sid[r] * C + f];
            sc  += w;
            g_Cb[(size_t)(base + r) * C + f] = acc;
            if (f == 0) g_e1c[base + r] = sc;
        }
    }
}

// ---------------- kernel 4: segment offsets ----------------
__global__ __launch_bounds__(C) void offsets_kernel()
{
    const int b = blockIdx.x;
    const int f = threadIdx.x;

    float accF = 0.f;
    for (int s = 0; s < NSEG; s++) {
        g_Of[(size_t)(b * NSEG + s) * C + f] = accF;
        accF += g_Cf[(size_t)(b * N + s * SEG + SEG - 1) * C + f];
    }
    float accB = 0.f;
    for (int s = NSEG - 1; s >= 0; s--) {
        g_Ob[(size_t)(b * NSEG + s) * C + f] = accB;
        accB += g_Cb[(size_t)(b * N + s * SEG) * C + f];
    }
    if (f == 0) {
        float aF = 0.f;
        for (int s = 0; s < NSEG; s++) {
            g_of_sc[b * NSEG + s] = aF;
            aF += g_e2c[b * N + s * SEG + SEG - 1];
        }
        float aB = 0.f;
        for (int s = NSEG - 1; s >= 0; s--) {
            g_ob_sc[b * NSEG + s] = aB;
            aB += g_e1c[b * N + s * SEG];
        }
    }
}

// ---------------- kernel 5: per-row combine + ELU ----------------
__global__ __launch_bounds__(C) void out_kernel(float* __restrict__ out)
{
    const int b  = blockIdx.y;
    const int i0 = blockIdx.x * 64;
    const int f  = threadIdx.x;

    __shared__ float sk[N];
    for (int r = f; r < N; r += C) sk[r] = g_s2s[b * N + r];
    __syncthreads();

    const float m = g_m[b];

    for (int ii = 0; ii < 64; ii++) {
        const int i = i0 + ii;
        const float c  = g_s1[b * N + i];
        const float th = -c;

        // lower_bound: first r with sk[r] >= th (positive branch = suffix [k0, N))
        int lo = 0, hi = N;
        while (lo < hi) {
            int mid = (lo + hi) >> 1;
            if (sk[mid] < th) lo = mid + 1; else hi = mid;
        }
        const int k0 = lo;

        // stabilize by emax = lrelu(c + m) = max_j e_ij
        float cm = c + m;
        float emax = (cm >= 0.f) ? cm : ALPHA * cm;
        float A  = expf(cm - emax);            // <= 1
        float Bc = expf(ALPHA * cm - emax);    // <= 1

        float EH1 = 0.f, E1 = 0.f, EH2 = 0.f, E2 = 0.f;
        if (k0 < N) {
            int seg = k0 >> 7;
            EH1 = g_Cb[(size_t)(b * N + k0) * C + f] + g_Ob[(size_t)(b * NSEG + seg) * C + f];
            E1  = g_e1c[b * N + k0] + g_ob_sc[b * NSEG + seg];
        }
        if (k0 > 0) {
            int k1 = k0 - 1;
            int seg = k1 >> 7;
            EH2 = g_Cf[(size_t)(b * N + k1) * C + f] + g_Of[(size_t)(b * NSEG + seg) * C + f];
            E2  = g_e2c[b * N + k1] + g_of_sc[b * NSEG + seg];
        }

        float den = A * E1 + Bc * E2;          // >= 1 by construction
        float num = A * EH1 + Bc * EH2;
        float hp  = num / den;
        float x   = hp + ALPHA * g_h[(size_t)(b * N + i) * C + f];
        out[(size_t)(b * N + i) * C + f] = (x > 0.f) ? x : expm1f(x);
    }
}

// ---------------- launch ----------------
extern "C" void kernel_launch(void* const* d_in, const int* in_sizes, int n_in,
                              void* d_out, int out_size)
{
    const float* text = (const float*)d_in[0];   // [8, 2048, 128]
    // d_in[1] = adj (all-ones, unused by the reference -> never read)
    const float* W    = (const float*)d_in[2];   // [128, 128]
    const float* a    = (const float*)d_in[3];   // [256, 1]
    float* out        = (float*)d_out;           // [8, 2048, 128]

    gemm_s_kernel<<<(B * N) / 64, 256>>>(text, W, a);
    sort_kernel<<<B, 1024>>>();
    scan_kernel<<<dim3(NSEG, B), 256>>>();
    offsets_kernel<<<B, C>>>();
    out_kernel<<<dim3(N / 64, B), C>>>(out);
}

// round 6
// speedup vs baseline: 2.3251x; 2.3251x over previous
#include <cuda_runtime.h>
#include <math.h>

#define ALPHA 0.2f

constexpr int B = 8;
constexpr int N = 2048;
constexpr int C = 128;
constexpr int SEG = 64;
constexpr int NSEG = N / SEG;   // 32  (fits one warp)

// ---------------- device scratch ----------------
__device__ float g_h[B * N * C];
__device__ float g_s1[B * N];
__device__ float g_s2[B * N];
__device__ float g_s2s[B * N];            // sorted s2 (ascending) per batch
__device__ int   g_sidx[B * N];
__device__ float g_u[B * N];              // exp(s2s - m)
__device__ float g_v[B * N];              // exp(ALPHA*(s2s - m))
__device__ float g_Cf[B * N * C];         // fwd (v-weighted) inclusive seg-scan of h[sidx]
__device__ float g_Cb[B * N * C];         // bwd (u-weighted) inclusive seg-scan of h[sidx]
__device__ float g_e2c[B * N];
__device__ float g_e1c[B * N];
__device__ float g_Of[B * NSEG * C];
__device__ float g_Ob[B * NSEG * C];
__device__ float g_of_sc[B * NSEG];
__device__ float g_ob_sc[B * NSEG];
__device__ float g_m[B];
__device__ int   g_k0[B * N];             // clamped suffix start
__device__ int   g_k1[B * N];             // clamped prefix end
__device__ float g_rA[B * N];             // A/den (0 if suffix empty)
__device__ float g_rB[B * N];             // Bc/den (0 if prefix empty)

// ---------------- kernel 1: h = X @ W, fused s1/s2 ----------------
__global__ __launch_bounds__(256) void gemm_s_kernel(
    const float* __restrict__ X, const float* __restrict__ W,
    const float* __restrict__ a)
{
    __shared__ float Xs[64][C];
    __shared__ float Ws[16][C];

    const int t    = threadIdx.x;
    const int lane = t & 31;
    const int w    = t >> 5;
    const int cbase = lane * 4;
    const int rbase = w * 8;
    const int bm = blockIdx.x * 64;

    {
        const float4* Xg4 = reinterpret_cast<const float4*>(X + (size_t)bm * C);
        float4* Xs4 = reinterpret_cast<float4*>(&Xs[0][0]);
#pragma unroll
        for (int i = 0; i < 8; i++) Xs4[t + i * 256] = Xg4[t + i * 256];
    }

    float acc[8][4];
#pragma unroll
    for (int i = 0; i < 8; i++)
#pragma unroll
        for (int j = 0; j < 4; j++) acc[i][j] = 0.f;

    for (int k0 = 0; k0 < C; k0 += 16) {
        __syncthreads();
        {
            const float4* Wg4 = reinterpret_cast<const float4*>(W + (size_t)k0 * C);
            float4* Ws4 = reinterpret_cast<float4*>(&Ws[0][0]);
#pragma unroll
            for (int i = 0; i < 2; i++) Ws4[t + i * 256] = Wg4[t + i * 256];
        }
        __syncthreads();
#pragma unroll
        for (int kk = 0; kk < 16; kk++) {
            float4 wv = *reinterpret_cast<float4*>(&Ws[kk][cbase]);
#pragma unroll
            for (int i = 0; i < 8; i++) {
                float x = Xs[rbase + i][k0 + kk];
                acc[i][0] += x * wv.x;
                acc[i][1] += x * wv.y;
                acc[i][2] += x * wv.z;
                acc[i][3] += x * wv.w;
            }
        }
    }

#pragma unroll
    for (int i = 0; i < 8; i++) {
        float4 o = make_float4(acc[i][0], acc[i][1], acc[i][2], acc[i][3]);
        *reinterpret_cast<float4*>(&g_h[(size_t)(bm + rbase + i) * C + cbase]) = o;
    }

    float4 a1v = *reinterpret_cast<const float4*>(&a[cbase]);
    float4 a2v = *reinterpret_cast<const float4*>(&a[C + cbase]);
#pragma unroll
    for (int i = 0; i < 8; i++) {
        float p1 = acc[i][0] * a1v.x + acc[i][1] * a1v.y + acc[i][2] * a1v.z + acc[i][3] * a1v.w;
        float p2 = acc[i][0] * a2v.x + acc[i][1] * a2v.y + acc[i][2] * a2v.z + acc[i][3] * a2v.w;
#pragma unroll
        for (int o = 16; o; o >>= 1) {
            p1 += __shfl_xor_sync(0xffffffffu, p1, o);
            p2 += __shfl_xor_sync(0xffffffffu, p2, o);
        }
        if (lane == 0) {
            g_s1[bm + rbase + i] = p1;
            g_s2[bm + rbase + i] = p2;
        }
    }
}

// ---------------- kernel 2: per-batch bitonic sort + u,v,m ----------------
__global__ __launch_bounds__(1024) void sort_kernel()
{
    __shared__ float key[N];
    __shared__ int   idx[N];
    const int b = blockIdx.x;
    const int t = threadIdx.x;

    for (int e = t; e < N; e += 1024) { key[e] = g_s2[b * N + e]; idx[e] = e; }
    __syncthreads();

    for (int k = 2; k <= N; k <<= 1) {
        for (int j = k >> 1; j > 0; j >>= 1) {
#pragma unroll
            for (int half = 0; half < 2; half++) {
                int e = t + half * 1024;
                int ixj = e ^ j;
                if (ixj > e) {
                    bool up = ((e & k) == 0);
                    float ka = key[e], kb = key[ixj];
                    bool sw = up ? (ka > kb) : (ka < kb);
                    if (sw) {
                        key[e] = kb; key[ixj] = ka;
                        int tmp = idx[e]; idx[e] = idx[ixj]; idx[ixj] = tmp;
                    }
                }
            }
            __syncthreads();
        }
    }

    float m = key[N - 1];
    for (int e = t; e < N; e += 1024) {
        float s = key[e];
        g_s2s[b * N + e]  = s;
        g_sidx[b * N + e] = idx[e];
        g_u[b * N + e] = expf(s - m);
        g_v[b * N + e] = expf(ALPHA * (s - m));
    }
    if (t == 0) g_m[b] = m;
}

// ---------------- kernel 3: segmented fwd(v)/bwd(u) scans (SEG=64) ----------------
__global__ __launch_bounds__(256) void scan_kernel()
{
    const int b = blockIdx.y;
    const int s = blockIdx.x;
    const int t = threadIdx.x;

    __shared__ float wv[SEG];
    __shared__ float wu[SEG];
    __shared__ int   sid[SEG];

    const int base = b * N + s * SEG;
    if (t < SEG)            { wv[t] = g_v[base + t]; sid[t] = g_sidx[base + t]; }
    else if (t < 2 * SEG)   { wu[t - SEG] = g_u[base + (t - SEG)]; }
    __syncthreads();

    const float* __restrict__ hb = g_h + (size_t)b * N * C;

    if (t < C) {                           // forward, v-weighted
        const int f = t;
        float acc = 0.f, sc = 0.f;
#pragma unroll 4
        for (int r = 0; r < SEG; r++) {
            float w = wv[r];
            acc += w * hb[(size_t)sid[r] * C + f];
            sc  += w;
            g_Cf[(size_t)(base + r) * C + f] = acc;
            if (f == 0) g_e2c[base + r] = sc;
        }
    } else {                               // backward, u-weighted
        const int f = t - C;
        float acc = 0.f, sc = 0.f;
#pragma unroll 4
        for (int r = SEG - 1; r >= 0; r--) {
            float w = wu[r];
            acc += w * hb[(size_t)sid[r] * C + f];
            sc  += w;
            g_Cb[(size_t)(base + r) * C + f] = acc;
            if (f == 0) g_e1c[base + r] = sc;
        }
    }
}

// ---------------- kernel 4: segment offsets via warp scans ----------------
// one warp per (b, f): 32 lanes = 32 segments. B*C = 1024 warps -> 128 blocks.
__global__ __launch_bounds__(256) void offsets_kernel()
{
    const int w    = blockIdx.x * 8 + (threadIdx.x >> 5);   // 0..1023
    const int lane = threadIdx.x & 31;                      // segment index
    const int b = w >> 7;          // / C
    const int f = w & (C - 1);

    // forward: exclusive prefix of segment totals (total = Cf at seg end)
    float tf = g_Cf[(size_t)(b * N + lane * SEG + SEG - 1) * C + f];
    float x = tf;
#pragma unroll
    for (int o = 1; o < 32; o <<= 1) {
        float y = __shfl_up_sync(0xffffffffu, x, o);
        if (lane >= o) x += y;
    }
    g_Of[(size_t)(b * NSEG + lane) * C + f] = x - tf;

    // backward: exclusive suffix of segment totals (total = Cb at seg start)
    float tb = g_Cb[(size_t)(b * N + lane * SEG) * C + f];
    float xb = tb;
#pragma unroll
    for (int o = 1; o < 32; o <<= 1) {
        float y = __shfl_down_sync(0xffffffffu, xb, o);
        if (lane < 32 - o) xb += y;
    }
    g_Ob[(size_t)(b * NSEG + lane) * C + f] = xb - tb;

    if (f == 0) {   // scalar tables (uniform per warp)
        float ts = g_e2c[b * N + lane * SEG + SEG - 1];
        float xs = ts;
#pragma unroll
        for (int o = 1; o < 32; o <<= 1) {
            float y = __shfl_up_sync(0xffffffffu, xs, o);
            if (lane >= o) xs += y;
        }
        g_of_sc[b * NSEG + lane] = xs - ts;

        float tbs = g_e1c[b * N + lane * SEG];
        float xbs = tbs;
#pragma unroll
        for (int o = 1; o < 32; o <<= 1) {
            float y = __shfl_down_sync(0xffffffffu, xbs, o);
            if (lane < 32 - o) xbs += y;
        }
        g_ob_sc[b * NSEG + lane] = xbs - tbs;
    }
}

// ---------------- kernel 5: per-row coefficients (binary search + scalars) ----------------
// one thread per row; block covers 256 consecutive rows of one batch.
__global__ __launch_bounds__(256) void row_kernel()
{
    const int gid = blockIdx.x * 256 + threadIdx.x;   // b*N + i
    const int b   = gid >> 11;

    __shared__ float sk[N];
    for (int r = threadIdx.x; r < N; r += 256) sk[r] = g_s2s[b * N + r];
    __syncthreads();

    const float c  = g_s1[gid];
    const float th = -c;

    int lo = 0, hi = N;
    while (lo < hi) {
        int mid = (lo + hi) >> 1;
        if (sk[mid] < th) lo = mid + 1; else hi = mid;
    }
    const int k0 = lo;   // positive branch = suffix [k0, N)

    const float m  = g_m[b];
    const float cm = c + m;
    const float emax = (cm >= 0.f) ? cm : ALPHA * cm;
    const float A  = expf(cm - emax);
    const float Bc = expf(ALPHA * cm - emax);

    float E1 = 0.f, E2 = 0.f;
    if (k0 < N) E1 = g_e1c[b * N + k0] + g_ob_sc[b * NSEG + (k0 >> 6)];
    if (k0 > 0) {
        int k1 = k0 - 1;
        E2 = g_e2c[b * N + k1] + g_of_sc[b * NSEG + (k1 >> 6)];
    }
    const float den = A * E1 + Bc * E2;

    g_rA[gid] = (k0 < N) ? (A / den)  : 0.f;
    g_rB[gid] = (k0 > 0) ? (Bc / den) : 0.f;
    g_k0[gid] = (k0 < N) ? k0 : (N - 1);   // clamped: garbage*0 stays finite
    g_k1[gid] = (k0 > 0) ? (k0 - 1) : 0;
}

// ---------------- kernel 6: streaming elementwise combine + ELU ----------------
__global__ __launch_bounds__(256) void out_kernel(float* __restrict__ out)
{
    const int gid = blockIdx.x * 256 + threadIdx.x;   // element index
    const int row = gid >> 7;                         // b*N + i
    const int f   = gid & (C - 1);
    const int b   = row >> 11;
    const int base = row & ~(N - 1);                  // b*N

    const int   k0 = g_k0[row];
    const int   k1 = g_k1[row];
    const float rA = g_rA[row];
    const float rB = g_rB[row];

    const float EH1 = g_Cb[(size_t)(base + k0) * C + f]
                    + g_Ob[(size_t)(b * NSEG + (k0 >> 6)) * C + f];
    const float EH2 = g_Cf[(size_t)(base + k1) * C + f]
                    + g_Of[(size_t)(b * NSEG + (k1 >> 6)) * C + f];

    const float hp = rA * EH1 + rB * EH2;
    const float x  = hp + ALPHA * g_h[gid];
    out[gid] = (x > 0.f) ? x : expm1f(x);
}

// ---------------- launch ----------------
extern "C" void kernel_launch(void* const* d_in, const int* in_sizes, int n_in,
                              void* d_out, int out_size)
{
    const float* text = (const float*)d_in[0];   // [8, 2048, 128]
    // d_in[1] = adj (all-ones, unused by the reference -> never read)
    const float* W    = (const float*)d_in[2];   // [128, 128]
    const float* a    = (const float*)d_in[3];   // [256, 1]
    float* out        = (float*)d_out;           // [8, 2048, 128]

    gemm_s_kernel<<<(B * N) / 64, 256>>>(text, W, a);
    sort_kernel<<<B, 1024>>>();
    scan_kernel<<<dim3(NSEG, B), 256>>>();
    offsets_kernel<<<(B * C) / 8, 256>>>();
    row_kernel<<<(B * N) / 256, 256>>>();
    out_kernel<<<(B * N * C) / 256, 256>>>(out);
}